// round 1
// baseline (speedup 1.0000x reference)
#include <cuda_runtime.h>
#include <cuda_bf16.h>
#include <math.h>

// Problem constants
#define BATCH   2
#define SEQ     2048
#define DMODEL  1024
#define NHEADS  16
#define HDIM    64
#define NTOK    (BATCH * SEQ)          // 4096

// ---------------------------------------------------------------------------
// Scratch (device globals — no runtime allocation allowed)
// ---------------------------------------------------------------------------
__device__ float g_q[NTOK * DMODEL];
__device__ float g_k[NTOK * DMODEL];
__device__ float g_v[NTOK * DMODEL];
__device__ float g_o[NTOK * DMODEL];

// ---------------------------------------------------------------------------
// GEMM:  C[M,N] = A[M,K] * W[N,K]^T + bias[N]   (torch Linear, NT layout)
// 128x128 block tile, BK=8, 256 threads, 8x8 register tile.
// ---------------------------------------------------------------------------
#define BM 128
#define BN 128
#define BK 8

__global__ __launch_bounds__(256) void gemm_nt_bias(
    const float* __restrict__ A, const float* __restrict__ W,
    const float* __restrict__ bias, float* __restrict__ C,
    int M, int N, int K)
{
    __shared__ __align__(16) float As[BK][BM];
    __shared__ __align__(16) float Bs[BK][BN];

    const int bm = blockIdx.y * BM;
    const int bn = blockIdx.x * BN;
    const int tid = threadIdx.x;

    // loader mapping: each thread loads one float4 of A and one of W per k-tile
    const int lr = tid >> 1;          // 0..127  (row within tile)
    const int lc = (tid & 1) * 4;     // 0 or 4  (col within BK)

    const int ty = tid >> 4;          // 0..15
    const int tx = tid & 15;          // 0..15

    float acc[8][8];
    #pragma unroll
    for (int i = 0; i < 8; i++)
        #pragma unroll
        for (int j = 0; j < 8; j++) acc[i][j] = 0.f;

    for (int k0 = 0; k0 < K; k0 += BK) {
        float4 a4 = *(const float4*)&A[(size_t)(bm + lr) * K + k0 + lc];
        float4 w4 = *(const float4*)&W[(size_t)(bn + lr) * K + k0 + lc];
        As[lc + 0][lr] = a4.x; As[lc + 1][lr] = a4.y;
        As[lc + 2][lr] = a4.z; As[lc + 3][lr] = a4.w;
        Bs[lc + 0][lr] = w4.x; Bs[lc + 1][lr] = w4.y;
        Bs[lc + 2][lr] = w4.z; Bs[lc + 3][lr] = w4.w;
        __syncthreads();

        #pragma unroll
        for (int kk = 0; kk < BK; kk++) {
            float4 a0 = *(const float4*)&As[kk][ty * 8];
            float4 a1 = *(const float4*)&As[kk][ty * 8 + 4];
            float4 b0 = *(const float4*)&Bs[kk][tx * 8];
            float4 b1 = *(const float4*)&Bs[kk][tx * 8 + 4];
            float ra[8] = {a0.x, a0.y, a0.z, a0.w, a1.x, a1.y, a1.z, a1.w};
            float rb[8] = {b0.x, b0.y, b0.z, b0.w, b1.x, b1.y, b1.z, b1.w};
            #pragma unroll
            for (int i = 0; i < 8; i++)
                #pragma unroll
                for (int j = 0; j < 8; j++)
                    acc[i][j] = fmaf(ra[i], rb[j], acc[i][j]);
        }
        __syncthreads();
    }

    // epilogue: add bias, store float4
    #pragma unroll
    for (int i = 0; i < 8; i++) {
        const int row = bm + ty * 8 + i;
        float* cptr = &C[(size_t)row * N + bn + tx * 8];
        const float* bptr = &bias[bn + tx * 8];
        float4 c0, c1;
        c0.x = acc[i][0] + bptr[0]; c0.y = acc[i][1] + bptr[1];
        c0.z = acc[i][2] + bptr[2]; c0.w = acc[i][3] + bptr[3];
        c1.x = acc[i][4] + bptr[4]; c1.y = acc[i][5] + bptr[5];
        c1.z = acc[i][6] + bptr[6]; c1.w = acc[i][7] + bptr[7];
        *(float4*)(cptr)     = c0;
        *(float4*)(cptr + 4) = c1;
    }
}

// ---------------------------------------------------------------------------
// RoPE: one warp per (b, t, h).  Pair (i, i+32), i = lane.
//   q'[i]    = q[i]*cos - q[i+32]*sin
//   q'[i+32] = q[i+32]*cos + q[i]*sin
// angle = t * 10000^(-2i/64), matching the fp32 JAX reference.
// ---------------------------------------------------------------------------
__global__ __launch_bounds__(256) void rope_kernel(float* __restrict__ q,
                                                   float* __restrict__ k)
{
    const int gtid = blockIdx.x * blockDim.x + threadIdx.x;
    const int warp = gtid >> 5;
    const int lane = gtid & 31;
    // warp -> (b, t, h)
    const int h = warp % NHEADS;
    const int t = (warp / NHEADS) % SEQ;
    const int b = warp / (NHEADS * SEQ);

    const float inv_freq = powf(10000.0f, -(float)(2 * lane) / (float)HDIM);
    const float ang = (float)t * inv_freq;
    float c, s;
    __sincosf(ang, &s, &c);
    // __sincosf is the fast path; for closer match to fp32 libm use sincosf:
    s = sinf(ang); c = cosf(ang);

    const size_t base = ((size_t)(b * SEQ + t)) * DMODEL + h * HDIM;

    float q1 = q[base + lane], q2 = q[base + lane + 32];
    q[base + lane]      = q1 * c - q2 * s;
    q[base + lane + 32] = q2 * c + q1 * s;

    float k1 = k[base + lane], k2 = k[base + lane + 32];
    k[base + lane]      = k1 * c - k2 * s;
    k[base + lane + 32] = k2 * c + k1 * s;
}

// ---------------------------------------------------------------------------
// Attention (non-causal, full softmax), flash-style fp32.
// Block: 256 threads = 8 warps. Each warp owns one query row.
// Block loops over K/V in 64-row SMEM tiles shared by all 8 warps.
// Per warp: lane computes scores for k-rows (lane, lane+32); online softmax;
// PV accumulated with lane owning output dims (2*lane, 2*lane+1).
// ---------------------------------------------------------------------------
#define WPB 8
#define KTILE 64

__global__ __launch_bounds__(256) void attn_kernel(
    const float* __restrict__ Q, const float* __restrict__ K,
    const float* __restrict__ V, float* __restrict__ O)
{
    __shared__ __align__(16) float q_s[WPB][HDIM];
    __shared__ float k_s[KTILE][HDIM + 1];   // pad 65: conflict-free row reads
    __shared__ float v_s[KTILE][HDIM + 2];   // pad 66: conflict-free float2 col reads
    __shared__ float p_s[WPB][KTILE];

    const int tid  = threadIdx.x;
    const int w    = tid >> 5;
    const int lane = tid & 31;
    const int b = blockIdx.z;
    const int h = blockIdx.y;
    const int q_row0 = blockIdx.x * WPB;

    // load 8 query rows (2 floats per thread)
    {
        const int r = tid >> 5;
        const int d = (tid & 31) * 2;
        const float* qp = Q + ((size_t)(b * SEQ + q_row0 + r)) * DMODEL + h * HDIM + d;
        q_s[r][d] = qp[0]; q_s[r][d + 1] = qp[1];
    }

    float m = -INFINITY, l = 0.f, o0 = 0.f, o1 = 0.f;
    const float scale = 0.125f;   // 1/sqrt(64)

    for (int j0 = 0; j0 < SEQ; j0 += KTILE) {
        __syncthreads();   // protect previous tile use (and q_s load on iter 0)
        // cooperative load of K/V tiles: 1024 float4 each over 256 threads
        for (int i = tid; i < KTILE * (HDIM / 4); i += 256) {
            const int r = i >> 4;
            const int f = (i & 15) * 4;
            const size_t g = ((size_t)(b * SEQ + j0 + r)) * DMODEL + h * HDIM + f;
            float4 kk4 = *(const float4*)(K + g);
            float4 vv4 = *(const float4*)(V + g);
            k_s[r][f+0] = kk4.x; k_s[r][f+1] = kk4.y; k_s[r][f+2] = kk4.z; k_s[r][f+3] = kk4.w;
            v_s[r][f+0] = vv4.x; v_s[r][f+1] = vv4.y; v_s[r][f+2] = vv4.z; v_s[r][f+3] = vv4.w;
        }
        __syncthreads();

        // scores for k-rows lane and lane+32
        float s0 = 0.f, s1 = 0.f;
        #pragma unroll 16
        for (int d = 0; d < HDIM; d++) {
            const float qd = q_s[w][d];
            s0 = fmaf(qd, k_s[lane][d], s0);
            s1 = fmaf(qd, k_s[lane + 32][d], s1);
        }
        s0 *= scale; s1 *= scale;

        // online softmax update
        float tmax = fmaxf(s0, s1);
        #pragma unroll
        for (int off = 16; off > 0; off >>= 1)
            tmax = fmaxf(tmax, __shfl_xor_sync(0xffffffffu, tmax, off));
        const float m_new = fmaxf(m, tmax);
        const float alpha = __expf(m - m_new);
        const float p0 = __expf(s0 - m_new);
        const float p1 = __expf(s1 - m_new);
        float psum = p0 + p1;
        #pragma unroll
        for (int off = 16; off > 0; off >>= 1)
            psum += __shfl_xor_sync(0xffffffffu, psum, off);
        l = l * alpha + psum;
        m = m_new;

        p_s[w][lane] = p0;
        p_s[w][lane + 32] = p1;
        o0 *= alpha; o1 *= alpha;
        __syncwarp();

        // PV: lane owns dims (2*lane, 2*lane+1)
        #pragma unroll 16
        for (int j = 0; j < KTILE; j++) {
            const float p = p_s[w][j];
            const float2 vv = *(const float2*)&v_s[j][lane * 2];
            o0 = fmaf(p, vv.x, o0);
            o1 = fmaf(p, vv.y, o1);
        }
    }

    const float invl = 1.0f / l;
    float* op = O + ((size_t)(b * SEQ + q_row0 + w)) * DMODEL + h * HDIM + lane * 2;
    op[0] = o0 * invl;
    op[1] = o1 * invl;
}

// ---------------------------------------------------------------------------
// Launch
// Inputs (metadata order): q_in, k_in, v_in, Wq, bq, Wk, bk, Wv, bv, Wo, bo
// ---------------------------------------------------------------------------
extern "C" void kernel_launch(void* const* d_in, const int* in_sizes, int n_in,
                              void* d_out, int out_size)
{
    const float* q_in = (const float*)d_in[0];
    const float* k_in = (const float*)d_in[1];
    const float* v_in = (const float*)d_in[2];
    const float* Wq = (const float*)d_in[3];
    const float* bq = (const float*)d_in[4];
    const float* Wk = (const float*)d_in[5];
    const float* bk = (const float*)d_in[6];
    const float* Wv = (const float*)d_in[7];
    const float* bv = (const float*)d_in[8];
    const float* Wo = (const float*)d_in[9];
    const float* bo = (const float*)d_in[10];
    float* out = (float*)d_out;

    float *pq, *pk, *pv, *po;
    cudaGetSymbolAddress((void**)&pq, g_q);
    cudaGetSymbolAddress((void**)&pk, g_k);
    cudaGetSymbolAddress((void**)&pv, g_v);
    cudaGetSymbolAddress((void**)&po, g_o);

    dim3 gemm_grid(DMODEL / BN, NTOK / BM);   // (8, 32)
    gemm_nt_bias<<<gemm_grid, 256>>>(q_in, Wq, bq, pq, NTOK, DMODEL, DMODEL);
    gemm_nt_bias<<<gemm_grid, 256>>>(k_in, Wk, bk, pk, NTOK, DMODEL, DMODEL);
    gemm_nt_bias<<<gemm_grid, 256>>>(v_in, Wv, bv, pv, NTOK, DMODEL, DMODEL);

    // RoPE: one warp per (b,t,h) -> B*T*H = 65536 warps, 8 warps/block
    rope_kernel<<<(BATCH * SEQ * NHEADS) / 8, 256>>>(pq, pk);

    dim3 attn_grid(SEQ / WPB, NHEADS, BATCH); // (256, 16, 2)
    attn_kernel<<<attn_grid, 256>>>(pq, pk, pv, po);

    gemm_nt_bias<<<gemm_grid, 256>>>(po, Wo, bo, out, NTOK, DMODEL, DMODEL);
}

// round 4
// speedup vs baseline: 1.1678x; 1.1678x over previous
#include <cuda_runtime.h>
#include <cuda_bf16.h>
#include <math.h>
#include <stdint.h>

// Problem constants
#define BATCH   2
#define SEQ     2048
#define DMODEL  1024
#define NHEADS  16
#define HDIM    64
#define NTOK    (BATCH * SEQ)          // 4096

// ---------------------------------------------------------------------------
// Scratch (device globals — no runtime allocation allowed)
// ---------------------------------------------------------------------------
__device__ float g_q[NTOK * DMODEL];
__device__ float g_k[NTOK * DMODEL];
__device__ float g_v[NTOK * DMODEL];
__device__ float g_o[NTOK * DMODEL];

// ---------------------------------------------------------------------------
// Portable (sm_80+) tensor-core helpers: tf32 mma.sync — works on base sm_103
// ---------------------------------------------------------------------------
__device__ __forceinline__ uint32_t tf32_rna(float x) {
    uint32_t r;
    asm("cvt.rna.tf32.f32 %0, %1;" : "=r"(r) : "f"(x));
    return r;
}

#define MMA_TF32(d, a, b)                                                     \
    asm volatile("mma.sync.aligned.m16n8k8.row.col.f32.tf32.tf32.f32 "        \
        "{%0,%1,%2,%3}, {%4,%5,%6,%7}, {%8,%9}, {%0,%1,%2,%3};"               \
        : "+f"((d)[0]), "+f"((d)[1]), "+f"((d)[2]), "+f"((d)[3])              \
        : "r"((a)[0]), "r"((a)[1]), "r"((a)[2]), "r"((a)[3]),                 \
          "r"((b)[0]), "r"((b)[1]))

// ---------------------------------------------------------------------------
// tf32 GEMM: C[M,N] = rna_tf32(A[M,K]) * rna_tf32(W[N,K])^T + bias[N]
// CTA tile 128x128, BK=32, 512 threads (16 warps, 4x4), warp tile 32x32.
// Double-buffered SMEM (pitch 36 floats -> conflict-free fragment LDS).
// blockIdx.z selects one of up to 3 fused problems.
// ---------------------------------------------------------------------------
#define GPITCH 36                         // 32 + 4 pad floats per row
#define GTILEF (128 * GPITCH)             // floats per operand tile (4608)
#define GEMM_SMEM_BYTES (4 * GTILEF * 4)  // 2 bufs * (A+B) = 73728 bytes

__global__ void __launch_bounds__(512) gemm_tf32mma(
    const float* __restrict__ A0, const float* __restrict__ A1, const float* __restrict__ A2,
    const float* __restrict__ W0, const float* __restrict__ W1, const float* __restrict__ W2,
    const float* __restrict__ B0, const float* __restrict__ B1, const float* __restrict__ B2,
    float* __restrict__ C0, float* __restrict__ C1, float* __restrict__ C2)
{
    extern __shared__ __align__(16) float smf[];
    const int tid  = threadIdx.x;
    const int wid  = tid >> 5;
    const int lane = tid & 31;
    const int g    = lane >> 2;       // group id 0..7
    const int tg   = lane & 3;        // thread-in-group 0..3
    const int wm   = wid >> 2;        // warp row 0..3  (32 rows)
    const int wn   = wid & 3;         // warp col 0..3  (32 cols)
    const int z    = blockIdx.z;

    const float* A    = (z == 0) ? A0 : ((z == 1) ? A1 : A2);
    const float* W    = (z == 0) ? W0 : ((z == 1) ? W1 : W2);
    const float* bias = (z == 0) ? B0 : ((z == 1) ? B1 : B2);
    float*       C    = (z == 0) ? C0 : ((z == 1) ? C1 : C2);

    const int bm = blockIdx.y * 128;
    const int bn = blockIdx.x * 128;

    // global slot mapping: tile = 128 rows x 8 float4; thread owns slots tid, tid+512
    const int r0 = tid >> 3;          // 0..63
    const int f4 = tid & 7;           // float4 index in row

    float acc[2][4][4];
    #pragma unroll
    for (int mt = 0; mt < 2; mt++)
        #pragma unroll
        for (int nt = 0; nt < 4; nt++)
            #pragma unroll
            for (int i = 0; i < 4; i++) acc[mt][nt][i] = 0.f;

    // ---- load chunk 0 into buffer 0
    {
        const float* Ag = A + (size_t)bm * DMODEL;
        const float* Wg = W + (size_t)bn * DMODEL;
        float* As = smf;            // buf0 A
        float* Bs = smf + GTILEF;   // buf0 B
        #pragma unroll
        for (int s = 0; s < 2; s++) {
            const int row = r0 + s * 64;
            float4 a4 = *(const float4*)(Ag + (size_t)row * DMODEL + f4 * 4);
            float4 w4 = *(const float4*)(Wg + (size_t)row * DMODEL + f4 * 4);
            uint32_t* ap = (uint32_t*)(As + row * GPITCH + f4 * 4);
            uint32_t* bp = (uint32_t*)(Bs + row * GPITCH + f4 * 4);
            ap[0] = tf32_rna(a4.x); ap[1] = tf32_rna(a4.y);
            ap[2] = tf32_rna(a4.z); ap[3] = tf32_rna(a4.w);
            bp[0] = tf32_rna(w4.x); bp[1] = tf32_rna(w4.y);
            bp[2] = tf32_rna(w4.z); bp[3] = tf32_rna(w4.w);
        }
    }
    __syncthreads();

    #pragma unroll 1
    for (int c = 0; c < 32; c++) {
        // ---- prefetch chunk c+1 into registers
        float4 pa[2], pw[2];
        if (c < 31) {
            const float* Ag = A + (size_t)bm * DMODEL + (c + 1) * 32;
            const float* Wg = W + (size_t)bn * DMODEL + (c + 1) * 32;
            #pragma unroll
            for (int s = 0; s < 2; s++) {
                const int row = r0 + s * 64;
                pa[s] = *(const float4*)(Ag + (size_t)row * DMODEL + f4 * 4);
                pw[s] = *(const float4*)(Wg + (size_t)row * DMODEL + f4 * 4);
            }
        }

        // ---- compute on buffer c&1
        const float* As = smf + (c & 1) * (2 * GTILEF);
        const float* Bs = As + GTILEF;
        #pragma unroll
        for (int ks = 0; ks < 4; ks++) {
            const int k0 = ks * 8;
            uint32_t afr[2][4], bfr[4][2];
            #pragma unroll
            for (int mt = 0; mt < 2; mt++) {
                const int r = wm * 32 + mt * 16 + g;
                const uint32_t* Ar = (const uint32_t*)(As + r * GPITCH + k0);
                afr[mt][0] = Ar[tg];
                afr[mt][2] = Ar[tg + 4];
                const uint32_t* Ar8 = (const uint32_t*)(As + (r + 8) * GPITCH + k0);
                afr[mt][1] = Ar8[tg];
                afr[mt][3] = Ar8[tg + 4];
            }
            #pragma unroll
            for (int nt = 0; nt < 4; nt++) {
                const uint32_t* Br =
                    (const uint32_t*)(Bs + (wn * 32 + nt * 8 + g) * GPITCH + k0);
                bfr[nt][0] = Br[tg];
                bfr[nt][1] = Br[tg + 4];
            }
            #pragma unroll
            for (int mt = 0; mt < 2; mt++)
                #pragma unroll
                for (int nt = 0; nt < 4; nt++)
                    MMA_TF32(acc[mt][nt], afr[mt], bfr[nt]);
        }

        // ---- stage prefetch into the other buffer
        if (c < 31) {
            __syncthreads();
            float* Ad = smf + ((c + 1) & 1) * (2 * GTILEF);
            float* Bd = Ad + GTILEF;
            #pragma unroll
            for (int s = 0; s < 2; s++) {
                const int row = r0 + s * 64;
                uint32_t* ap = (uint32_t*)(Ad + row * GPITCH + f4 * 4);
                uint32_t* bp = (uint32_t*)(Bd + row * GPITCH + f4 * 4);
                ap[0] = tf32_rna(pa[s].x); ap[1] = tf32_rna(pa[s].y);
                ap[2] = tf32_rna(pa[s].z); ap[3] = tf32_rna(pa[s].w);
                bp[0] = tf32_rna(pw[s].x); bp[1] = tf32_rna(pw[s].y);
                bp[2] = tf32_rna(pw[s].z); bp[3] = tf32_rna(pw[s].w);
            }
            __syncthreads();
        }
    }

    // ---- epilogue: bias + store (float2 per fragment row)
    #pragma unroll
    for (int mt = 0; mt < 2; mt++) {
        const int row = bm + wm * 32 + mt * 16 + g;
        #pragma unroll
        for (int nt = 0; nt < 4; nt++) {
            const int col = bn + wn * 32 + nt * 8 + tg * 2;
            const float2 bv = *(const float2*)(bias + col);
            float2 o0, o1;
            o0.x = acc[mt][nt][0] + bv.x; o0.y = acc[mt][nt][1] + bv.y;
            o1.x = acc[mt][nt][2] + bv.x; o1.y = acc[mt][nt][3] + bv.y;
            *(float2*)(C + (size_t)row * DMODEL + col) = o0;
            *(float2*)(C + (size_t)(row + 8) * DMODEL + col) = o1;
        }
    }
}

// ---------------------------------------------------------------------------
// RoPE: one warp per (b, t, h).  Pair (i, i+32), i = lane.
// ---------------------------------------------------------------------------
__global__ __launch_bounds__(256) void rope_kernel(float* __restrict__ q,
                                                   float* __restrict__ k)
{
    const int gtid = blockIdx.x * blockDim.x + threadIdx.x;
    const int warp = gtid >> 5;
    const int lane = gtid & 31;
    const int h = warp % NHEADS;
    const int t = (warp / NHEADS) % SEQ;
    const int b = warp / (NHEADS * SEQ);

    const float inv_freq = powf(10000.0f, -(float)(2 * lane) / (float)HDIM);
    const float ang = (float)t * inv_freq;
    const float s = sinf(ang);
    const float c = cosf(ang);

    const size_t base = ((size_t)(b * SEQ + t)) * DMODEL + h * HDIM;

    float q1 = q[base + lane], q2 = q[base + lane + 32];
    q[base + lane]      = q1 * c - q2 * s;
    q[base + lane + 32] = q2 * c + q1 * s;

    float k1 = k[base + lane], k2 = k[base + lane + 32];
    k[base + lane]      = k1 * c - k2 * s;
    k[base + lane + 32] = k2 * c + k1 * s;
}

// ---------------------------------------------------------------------------
// Attention (non-causal, full softmax), flash-style fp32. (unchanged — known good)
// ---------------------------------------------------------------------------
#define WPB 8
#define KTILE 64

__global__ __launch_bounds__(256) void attn_kernel(
    const float* __restrict__ Q, const float* __restrict__ K,
    const float* __restrict__ V, float* __restrict__ O)
{
    __shared__ __align__(16) float q_s[WPB][HDIM];
    __shared__ float k_s[KTILE][HDIM + 1];
    __shared__ float v_s[KTILE][HDIM + 2];
    __shared__ float p_s[WPB][KTILE];

    const int tid  = threadIdx.x;
    const int w    = tid >> 5;
    const int lane = tid & 31;
    const int b = blockIdx.z;
    const int h = blockIdx.y;
    const int q_row0 = blockIdx.x * WPB;

    {
        const int r = tid >> 5;
        const int d = (tid & 31) * 2;
        const float* qp = Q + ((size_t)(b * SEQ + q_row0 + r)) * DMODEL + h * HDIM + d;
        q_s[r][d] = qp[0]; q_s[r][d + 1] = qp[1];
    }

    float m = -INFINITY, l = 0.f, o0 = 0.f, o1 = 0.f;
    const float scale = 0.125f;

    for (int j0 = 0; j0 < SEQ; j0 += KTILE) {
        __syncthreads();
        for (int i = tid; i < KTILE * (HDIM / 4); i += 256) {
            const int r = i >> 4;
            const int f = (i & 15) * 4;
            const size_t gg = ((size_t)(b * SEQ + j0 + r)) * DMODEL + h * HDIM + f;
            float4 kk4 = *(const float4*)(K + gg);
            float4 vv4 = *(const float4*)(V + gg);
            k_s[r][f+0] = kk4.x; k_s[r][f+1] = kk4.y; k_s[r][f+2] = kk4.z; k_s[r][f+3] = kk4.w;
            v_s[r][f+0] = vv4.x; v_s[r][f+1] = vv4.y; v_s[r][f+2] = vv4.z; v_s[r][f+3] = vv4.w;
        }
        __syncthreads();

        float s0 = 0.f, s1 = 0.f;
        #pragma unroll 16
        for (int d = 0; d < HDIM; d++) {
            const float qd = q_s[w][d];
            s0 = fmaf(qd, k_s[lane][d], s0);
            s1 = fmaf(qd, k_s[lane + 32][d], s1);
        }
        s0 *= scale; s1 *= scale;

        float tmax = fmaxf(s0, s1);
        #pragma unroll
        for (int off = 16; off > 0; off >>= 1)
            tmax = fmaxf(tmax, __shfl_xor_sync(0xffffffffu, tmax, off));
        const float m_new = fmaxf(m, tmax);
        const float alpha = __expf(m - m_new);
        const float p0 = __expf(s0 - m_new);
        const float p1 = __expf(s1 - m_new);
        float psum = p0 + p1;
        #pragma unroll
        for (int off = 16; off > 0; off >>= 1)
            psum += __shfl_xor_sync(0xffffffffu, psum, off);
        l = l * alpha + psum;
        m = m_new;

        p_s[w][lane] = p0;
        p_s[w][lane + 32] = p1;
        o0 *= alpha; o1 *= alpha;
        __syncwarp();

        #pragma unroll 16
        for (int j = 0; j < KTILE; j++) {
            const float p = p_s[w][j];
            const float2 vv = *(const float2*)&v_s[j][lane * 2];
            o0 = fmaf(p, vv.x, o0);
            o1 = fmaf(p, vv.y, o1);
        }
    }

    const float invl = 1.0f / l;
    float* op = O + ((size_t)(b * SEQ + q_row0 + w)) * DMODEL + h * HDIM + lane * 2;
    op[0] = o0 * invl;
    op[1] = o1 * invl;
}

// ---------------------------------------------------------------------------
// Launch
// Inputs (metadata order): q_in, k_in, v_in, Wq, bq, Wk, bk, Wv, bv, Wo, bo
// ---------------------------------------------------------------------------
extern "C" void kernel_launch(void* const* d_in, const int* in_sizes, int n_in,
                              void* d_out, int out_size)
{
    const float* q_in = (const float*)d_in[0];
    const float* k_in = (const float*)d_in[1];
    const float* v_in = (const float*)d_in[2];
    const float* Wq = (const float*)d_in[3];
    const float* bq = (const float*)d_in[4];
    const float* Wk = (const float*)d_in[5];
    const float* bk = (const float*)d_in[6];
    const float* Wv = (const float*)d_in[7];
    const float* bv = (const float*)d_in[8];
    const float* Wo = (const float*)d_in[9];
    const float* bo = (const float*)d_in[10];
    float* out = (float*)d_out;

    float *pq, *pk, *pv, *po;
    cudaGetSymbolAddress((void**)&pq, g_q);
    cudaGetSymbolAddress((void**)&pk, g_k);
    cudaGetSymbolAddress((void**)&pv, g_v);
    cudaGetSymbolAddress((void**)&po, g_o);

    cudaFuncSetAttribute(gemm_tf32mma,
                         cudaFuncAttributeMaxDynamicSharedMemorySize, GEMM_SMEM_BYTES);

    // Fused Q/K/V projections: grid.z picks the problem
    dim3 qkv_grid(DMODEL / 128, NTOK / 128, 3);   // (8, 32, 3)
    gemm_tf32mma<<<qkv_grid, 512, GEMM_SMEM_BYTES>>>(
        q_in, k_in, v_in, Wq, Wk, Wv, bq, bk, bv, pq, pk, pv);

    rope_kernel<<<(BATCH * SEQ * NHEADS) / 8, 256>>>(pq, pk);

    dim3 attn_grid(SEQ / WPB, NHEADS, BATCH);     // (256, 16, 2)
    attn_kernel<<<attn_grid, 256>>>(pq, pk, pv, po);

    // Output projection (single problem in slot 0)
    dim3 o_grid(DMODEL / 128, NTOK / 128, 1);
    gemm_tf32mma<<<o_grid, 512, GEMM_SMEM_BYTES>>>(
        po, po, po, Wo, Wo, Wo, bo, bo, bo, out, out, out);
}

// round 6
// speedup vs baseline: 2.7973x; 2.3953x over previous
#include <cuda_runtime.h>
#include <cuda_bf16.h>
#include <math.h>
#include <stdint.h>

// Problem constants
#define BATCH   2
#define SEQ     2048
#define DMODEL  1024
#define NHEADS  16
#define HDIM    64
#define NTOK    (BATCH * SEQ)          // 4096

// ---------------------------------------------------------------------------
// Scratch (device globals — no runtime allocation allowed)
// ---------------------------------------------------------------------------
__device__ float g_q[NTOK * DMODEL];
__device__ float g_k[NTOK * DMODEL];
__device__ float g_v[NTOK * DMODEL];
__device__ float g_o[NTOK * DMODEL];

// ---------------------------------------------------------------------------
// Portable (sm_80+) tensor-core helpers: tf32 mma.sync — works on base sm_103
// ---------------------------------------------------------------------------
__device__ __forceinline__ uint32_t tf32_rna(float x) {
    uint32_t r;
    asm("cvt.rna.tf32.f32 %0, %1;" : "=r"(r) : "f"(x));
    return r;
}
__device__ __forceinline__ void split_tf32(float x, uint32_t& hi, uint32_t& lo) {
    hi = tf32_rna(x);
    lo = tf32_rna(x - __uint_as_float(hi));
}

#define MMA_TF32(d, a, b)                                                     \
    asm volatile("mma.sync.aligned.m16n8k8.row.col.f32.tf32.tf32.f32 "        \
        "{%0,%1,%2,%3}, {%4,%5,%6,%7}, {%8,%9}, {%0,%1,%2,%3};"               \
        : "+f"((d)[0]), "+f"((d)[1]), "+f"((d)[2]), "+f"((d)[3])              \
        : "r"((a)[0]), "r"((a)[1]), "r"((a)[2]), "r"((a)[3]),                 \
          "r"((b)[0]), "r"((b)[1]))

// ---------------------------------------------------------------------------
// tf32 GEMM: C[M,N] = rna_tf32(A[M,K]) * rna_tf32(W[N,K])^T + bias[N]
// (unchanged from round 4 — validated)
// ---------------------------------------------------------------------------
#define GPITCH 36
#define GTILEF (128 * GPITCH)
#define GEMM_SMEM_BYTES (4 * GTILEF * 4)

__global__ void __launch_bounds__(512) gemm_tf32mma(
    const float* __restrict__ A0, const float* __restrict__ A1, const float* __restrict__ A2,
    const float* __restrict__ W0, const float* __restrict__ W1, const float* __restrict__ W2,
    const float* __restrict__ B0, const float* __restrict__ B1, const float* __restrict__ B2,
    float* __restrict__ C0, float* __restrict__ C1, float* __restrict__ C2)
{
    extern __shared__ __align__(16) float smf[];
    const int tid  = threadIdx.x;
    const int wid  = tid >> 5;
    const int lane = tid & 31;
    const int g    = lane >> 2;
    const int tg   = lane & 3;
    const int wm   = wid >> 2;
    const int wn   = wid & 3;
    const int z    = blockIdx.z;

    const float* A    = (z == 0) ? A0 : ((z == 1) ? A1 : A2);
    const float* W    = (z == 0) ? W0 : ((z == 1) ? W1 : W2);
    const float* bias = (z == 0) ? B0 : ((z == 1) ? B1 : B2);
    float*       C    = (z == 0) ? C0 : ((z == 1) ? C1 : C2);

    const int bm = blockIdx.y * 128;
    const int bn = blockIdx.x * 128;

    const int r0 = tid >> 3;
    const int f4 = tid & 7;

    float acc[2][4][4];
    #pragma unroll
    for (int mt = 0; mt < 2; mt++)
        #pragma unroll
        for (int nt = 0; nt < 4; nt++)
            #pragma unroll
            for (int i = 0; i < 4; i++) acc[mt][nt][i] = 0.f;

    {
        const float* Ag = A + (size_t)bm * DMODEL;
        const float* Wg = W + (size_t)bn * DMODEL;
        float* As = smf;
        float* Bs = smf + GTILEF;
        #pragma unroll
        for (int s = 0; s < 2; s++) {
            const int row = r0 + s * 64;
            float4 a4 = *(const float4*)(Ag + (size_t)row * DMODEL + f4 * 4);
            float4 w4 = *(const float4*)(Wg + (size_t)row * DMODEL + f4 * 4);
            uint32_t* ap = (uint32_t*)(As + row * GPITCH + f4 * 4);
            uint32_t* bp = (uint32_t*)(Bs + row * GPITCH + f4 * 4);
            ap[0] = tf32_rna(a4.x); ap[1] = tf32_rna(a4.y);
            ap[2] = tf32_rna(a4.z); ap[3] = tf32_rna(a4.w);
            bp[0] = tf32_rna(w4.x); bp[1] = tf32_rna(w4.y);
            bp[2] = tf32_rna(w4.z); bp[3] = tf32_rna(w4.w);
        }
    }
    __syncthreads();

    #pragma unroll 1
    for (int c = 0; c < 32; c++) {
        float4 pa[2], pw[2];
        if (c < 31) {
            const float* Ag = A + (size_t)bm * DMODEL + (c + 1) * 32;
            const float* Wg = W + (size_t)bn * DMODEL + (c + 1) * 32;
            #pragma unroll
            for (int s = 0; s < 2; s++) {
                const int row = r0 + s * 64;
                pa[s] = *(const float4*)(Ag + (size_t)row * DMODEL + f4 * 4);
                pw[s] = *(const float4*)(Wg + (size_t)row * DMODEL + f4 * 4);
            }
        }

        const float* As = smf + (c & 1) * (2 * GTILEF);
        const float* Bs = As + GTILEF;
        #pragma unroll
        for (int ks = 0; ks < 4; ks++) {
            const int k0 = ks * 8;
            uint32_t afr[2][4], bfr[4][2];
            #pragma unroll
            for (int mt = 0; mt < 2; mt++) {
                const int r = wm * 32 + mt * 16 + g;
                const uint32_t* Ar = (const uint32_t*)(As + r * GPITCH + k0);
                afr[mt][0] = Ar[tg];
                afr[mt][2] = Ar[tg + 4];
                const uint32_t* Ar8 = (const uint32_t*)(As + (r + 8) * GPITCH + k0);
                afr[mt][1] = Ar8[tg];
                afr[mt][3] = Ar8[tg + 4];
            }
            #pragma unroll
            for (int nt = 0; nt < 4; nt++) {
                const uint32_t* Br =
                    (const uint32_t*)(Bs + (wn * 32 + nt * 8 + g) * GPITCH + k0);
                bfr[nt][0] = Br[tg];
                bfr[nt][1] = Br[tg + 4];
            }
            #pragma unroll
            for (int mt = 0; mt < 2; mt++)
                #pragma unroll
                for (int nt = 0; nt < 4; nt++)
                    MMA_TF32(acc[mt][nt], afr[mt], bfr[nt]);
        }

        if (c < 31) {
            __syncthreads();
            float* Ad = smf + ((c + 1) & 1) * (2 * GTILEF);
            float* Bd = Ad + GTILEF;
            #pragma unroll
            for (int s = 0; s < 2; s++) {
                const int row = r0 + s * 64;
                uint32_t* ap = (uint32_t*)(Ad + row * GPITCH + f4 * 4);
                uint32_t* bp = (uint32_t*)(Bd + row * GPITCH + f4 * 4);
                ap[0] = tf32_rna(pa[s].x); ap[1] = tf32_rna(pa[s].y);
                ap[2] = tf32_rna(pa[s].z); ap[3] = tf32_rna(pa[s].w);
                bp[0] = tf32_rna(pw[s].x); bp[1] = tf32_rna(pw[s].y);
                bp[2] = tf32_rna(pw[s].z); bp[3] = tf32_rna(pw[s].w);
            }
            __syncthreads();
        }
    }

    #pragma unroll
    for (int mt = 0; mt < 2; mt++) {
        const int row = bm + wm * 32 + mt * 16 + g;
        #pragma unroll
        for (int nt = 0; nt < 4; nt++) {
            const int col = bn + wn * 32 + nt * 8 + tg * 2;
            const float2 bv = *(const float2*)(bias + col);
            float2 o0, o1;
            o0.x = acc[mt][nt][0] + bv.x; o0.y = acc[mt][nt][1] + bv.y;
            o1.x = acc[mt][nt][2] + bv.x; o1.y = acc[mt][nt][3] + bv.y;
            *(float2*)(C + (size_t)row * DMODEL + col) = o0;
            *(float2*)(C + (size_t)(row + 8) * DMODEL + col) = o1;
        }
    }
}

// ---------------------------------------------------------------------------
// RoPE: one warp per (b, t, h). (unchanged — validated)
// ---------------------------------------------------------------------------
__global__ __launch_bounds__(256) void rope_kernel(float* __restrict__ q,
                                                   float* __restrict__ k)
{
    const int gtid = blockIdx.x * blockDim.x + threadIdx.x;
    const int warp = gtid >> 5;
    const int lane = gtid & 31;
    const int h = warp % NHEADS;
    const int t = (warp / NHEADS) % SEQ;
    const int b = warp / (NHEADS * SEQ);

    const float inv_freq = powf(10000.0f, -(float)(2 * lane) / (float)HDIM);
    const float ang = (float)t * inv_freq;
    const float s = sinf(ang);
    const float c = cosf(ang);

    const size_t base = ((size_t)(b * SEQ + t)) * DMODEL + h * HDIM;

    float q1 = q[base + lane], q2 = q[base + lane + 32];
    q[base + lane]      = q1 * c - q2 * s;
    q[base + lane + 32] = q2 * c + q1 * s;

    float k1 = k[base + lane], k2 = k[base + lane + 32];
    k[base + lane]      = k1 * c - k2 * s;
    k[base + lane + 32] = k2 * c + k1 * s;
}

// ---------------------------------------------------------------------------
// Tensor-core flash attention (tf32 mma.sync with 3-term error compensation).
// CTA: 256 threads = 8 warps; 128 q-rows (16/warp); K/V tiles of 64 keys.
// k_s [64][AP] natural, v_s [64][AP] transposed ([d][key]), p_s [128][AP].
// ---------------------------------------------------------------------------
#define AP 68
#define ATTN_SMEM_BYTES (256 * AP * 4)   // (64 + 64 + 128) rows * 68 * 4B = 69632

__global__ void __launch_bounds__(256) attn_tc(
    const float* __restrict__ Q, const float* __restrict__ K,
    const float* __restrict__ V, float* __restrict__ O)
{
    extern __shared__ __align__(16) float sm[];
    float* k_s = sm;                 // [64][AP]   k_s[key][d]
    float* v_s = sm + 64 * AP;       // [64][AP]   v_s[d][key]  (transposed)
    float* p_s = sm + 128 * AP;      // [128][AP]  p_s[qrow][key]

    const int tid  = threadIdx.x;
    const int w    = tid >> 5;
    const int lane = tid & 31;
    const int g    = lane >> 2;      // 0..7
    const int tg   = lane & 3;       // 0..3
    const int b    = blockIdx.z;
    const int h    = blockIdx.y;
    const int q0   = blockIdx.x * 128;

    // ---- Q fragments, hi/lo split, register-resident for the whole kernel
    uint32_t qh[8][4], ql[8][4];
    {
        const float* Qb = Q + ((size_t)(b * SEQ + q0 + w * 16)) * DMODEL + h * HDIM;
        #pragma unroll
        for (int ks = 0; ks < 8; ks++) {
            const int c0 = ks * 8 + tg;
            float f0 = Qb[(size_t)g * DMODEL + c0];
            float f1 = Qb[(size_t)(g + 8) * DMODEL + c0];
            float f2 = Qb[(size_t)g * DMODEL + c0 + 4];
            float f3 = Qb[(size_t)(g + 8) * DMODEL + c0 + 4];
            split_tf32(f0, qh[ks][0], ql[ks][0]);
            split_tf32(f1, qh[ks][1], ql[ks][1]);
            split_tf32(f2, qh[ks][2], ql[ks][2]);
            split_tf32(f3, qh[ks][3], ql[ks][3]);
        }
    }

    float out[8][4];
    #pragma unroll
    for (int nt = 0; nt < 8; nt++)
        #pragma unroll
        for (int i = 0; i < 4; i++) out[nt][i] = 0.f;
    float m0 = -INFINITY, m1 = -INFINITY, l0 = 0.f, l1 = 0.f;

    // V loader mapping: thread -> (key, dgroup)
    const int vkey = tid & 63;
    const int vdg  = tid >> 6;       // 0..3, covers 16 dims each

    #pragma unroll 1
    for (int j0 = 0; j0 < SEQ; j0 += 64) {
        __syncthreads();
        // ---- load K tile (natural layout)
        #pragma unroll
        for (int it = 0; it < 4; it++) {
            const int i   = it * 256 + tid;
            const int key = i >> 4;
            const int c4  = (i & 15) * 4;
            const float4 kk = *(const float4*)(
                K + ((size_t)(b * SEQ + j0 + key)) * DMODEL + h * HDIM + c4);
            *(float4*)(k_s + key * AP + c4) = kk;
        }
        // ---- load V tile transposed: v_s[d][key] (conflict-free STS)
        {
            const float* Vg = V + ((size_t)(b * SEQ + j0 + vkey)) * DMODEL + h * HDIM + vdg * 16;
            #pragma unroll
            for (int e = 0; e < 4; e++) {
                const float4 vv = *(const float4*)(Vg + e * 4);
                const int d0 = vdg * 16 + e * 4;
                v_s[(d0 + 0) * AP + vkey] = vv.x;
                v_s[(d0 + 1) * AP + vkey] = vv.y;
                v_s[(d0 + 2) * AP + vkey] = vv.z;
                v_s[(d0 + 3) * AP + vkey] = vv.w;
            }
        }
        __syncthreads();

        // ---- S = Q K^T (3xtf32)
        float s[8][4];
        #pragma unroll
        for (int nt = 0; nt < 8; nt++)
            #pragma unroll
            for (int i = 0; i < 4; i++) s[nt][i] = 0.f;

        #pragma unroll
        for (int ks = 0; ks < 8; ks++) {
            #pragma unroll
            for (int nt = 0; nt < 8; nt++) {
                const float b0f = k_s[(nt * 8 + g) * AP + ks * 8 + tg];
                const float b1f = k_s[(nt * 8 + g) * AP + ks * 8 + tg + 4];
                uint32_t bh[2], bl[2];
                split_tf32(b0f, bh[0], bl[0]);
                split_tf32(b1f, bh[1], bl[1]);
                MMA_TF32(s[nt], qh[ks], bh);
                MMA_TF32(s[nt], ql[ks], bh);
                MMA_TF32(s[nt], qh[ks], bl);
            }
        }

        // ---- online softmax (rows g and g+8)
        const float scale = 0.125f;
        float mt0 = -INFINITY, mt1 = -INFINITY;
        #pragma unroll
        for (int nt = 0; nt < 8; nt++) {
            s[nt][0] *= scale; s[nt][1] *= scale;
            s[nt][2] *= scale; s[nt][3] *= scale;
            mt0 = fmaxf(mt0, fmaxf(s[nt][0], s[nt][1]));
            mt1 = fmaxf(mt1, fmaxf(s[nt][2], s[nt][3]));
        }
        mt0 = fmaxf(mt0, __shfl_xor_sync(0xffffffffu, mt0, 1));
        mt0 = fmaxf(mt0, __shfl_xor_sync(0xffffffffu, mt0, 2));
        mt1 = fmaxf(mt1, __shfl_xor_sync(0xffffffffu, mt1, 1));
        mt1 = fmaxf(mt1, __shfl_xor_sync(0xffffffffu, mt1, 2));

        const float mn0 = fmaxf(m0, mt0);
        const float mn1 = fmaxf(m1, mt1);
        const float a0 = __expf(m0 - mn0);
        const float a1 = __expf(m1 - mn1);

        float rs0 = 0.f, rs1 = 0.f;
        float* pr0 = p_s + (w * 16 + g) * AP;
        float* pr1 = p_s + (w * 16 + g + 8) * AP;
        #pragma unroll
        for (int nt = 0; nt < 8; nt++) {
            const float p0 = __expf(s[nt][0] - mn0);
            const float p1 = __expf(s[nt][1] - mn0);
            const float p2 = __expf(s[nt][2] - mn1);
            const float p3 = __expf(s[nt][3] - mn1);
            rs0 += p0 + p1;
            rs1 += p2 + p3;
            *(float2*)(pr0 + nt * 8 + 2 * tg) = make_float2(p0, p1);
            *(float2*)(pr1 + nt * 8 + 2 * tg) = make_float2(p2, p3);
        }
        rs0 += __shfl_xor_sync(0xffffffffu, rs0, 1);
        rs0 += __shfl_xor_sync(0xffffffffu, rs0, 2);
        rs1 += __shfl_xor_sync(0xffffffffu, rs1, 1);
        rs1 += __shfl_xor_sync(0xffffffffu, rs1, 2);

        l0 = l0 * a0 + rs0;
        l1 = l1 * a1 + rs1;
        m0 = mn0;
        m1 = mn1;

        #pragma unroll
        for (int nt = 0; nt < 8; nt++) {
            out[nt][0] *= a0; out[nt][1] *= a0;
            out[nt][2] *= a1; out[nt][3] *= a1;
        }
        __syncwarp();

        // ---- out += P V (3xtf32); A-frag from p_s (warp-private rows)
        #pragma unroll
        for (int ks = 0; ks < 8; ks++) {
            const float af0 = p_s[(w * 16 + g) * AP + ks * 8 + tg];
            const float af1 = p_s[(w * 16 + g + 8) * AP + ks * 8 + tg];
            const float af2 = p_s[(w * 16 + g) * AP + ks * 8 + tg + 4];
            const float af3 = p_s[(w * 16 + g + 8) * AP + ks * 8 + tg + 4];
            uint32_t ah[4], al[4];
            split_tf32(af0, ah[0], al[0]);
            split_tf32(af1, ah[1], al[1]);
            split_tf32(af2, ah[2], al[2]);
            split_tf32(af3, ah[3], al[3]);
            #pragma unroll
            for (int nt = 0; nt < 8; nt++) {
                const float b0f = v_s[(nt * 8 + g) * AP + ks * 8 + tg];
                const float b1f = v_s[(nt * 8 + g) * AP + ks * 8 + tg + 4];
                uint32_t bh[2], bl[2];
                split_tf32(b0f, bh[0], bl[0]);
                split_tf32(b1f, bh[1], bl[1]);
                MMA_TF32(out[nt], ah, bh);
                MMA_TF32(out[nt], al, bh);
                MMA_TF32(out[nt], ah, bl);
            }
        }
    }

    // ---- epilogue: normalize and store
    const float inv0 = 1.f / l0;
    const float inv1 = 1.f / l1;
    const size_t tok0 = (size_t)(b * SEQ + q0 + w * 16 + g);
    #pragma unroll
    for (int nt = 0; nt < 8; nt++) {
        const int col = h * HDIM + nt * 8 + 2 * tg;
        *(float2*)(O + tok0 * DMODEL + col) =
            make_float2(out[nt][0] * inv0, out[nt][1] * inv0);
        *(float2*)(O + (tok0 + 8) * DMODEL + col) =
            make_float2(out[nt][2] * inv1, out[nt][3] * inv1);
    }
}

// ---------------------------------------------------------------------------
// Launch
// Inputs (metadata order): q_in, k_in, v_in, Wq, bq, Wk, bk, Wv, bv, Wo, bo
// ---------------------------------------------------------------------------
extern "C" void kernel_launch(void* const* d_in, const int* in_sizes, int n_in,
                              void* d_out, int out_size)
{
    const float* q_in = (const float*)d_in[0];
    const float* k_in = (const float*)d_in[1];
    const float* v_in = (const float*)d_in[2];
    const float* Wq = (const float*)d_in[3];
    const float* bq = (const float*)d_in[4];
    const float* Wk = (const float*)d_in[5];
    const float* bk = (const float*)d_in[6];
    const float* Wv = (const float*)d_in[7];
    const float* bv = (const float*)d_in[8];
    const float* Wo = (const float*)d_in[9];
    const float* bo = (const float*)d_in[10];
    float* out = (float*)d_out;

    float *pq, *pk, *pv, *po;
    cudaGetSymbolAddress((void**)&pq, g_q);
    cudaGetSymbolAddress((void**)&pk, g_k);
    cudaGetSymbolAddress((void**)&pv, g_v);
    cudaGetSymbolAddress((void**)&po, g_o);

    cudaFuncSetAttribute(gemm_tf32mma,
                         cudaFuncAttributeMaxDynamicSharedMemorySize, GEMM_SMEM_BYTES);
    cudaFuncSetAttribute(attn_tc,
                         cudaFuncAttributeMaxDynamicSharedMemorySize, ATTN_SMEM_BYTES);

    // Fused Q/K/V projections
    dim3 qkv_grid(DMODEL / 128, NTOK / 128, 3);
    gemm_tf32mma<<<qkv_grid, 512, GEMM_SMEM_BYTES>>>(
        q_in, k_in, v_in, Wq, Wk, Wv, bq, bk, bv, pq, pk, pv);

    rope_kernel<<<(BATCH * SEQ * NHEADS) / 8, 256>>>(pq, pk);

    // Tensor-core flash attention
    dim3 attn_grid(SEQ / 128, NHEADS, BATCH);     // (16, 16, 2)
    attn_tc<<<attn_grid, 256, ATTN_SMEM_BYTES>>>(pq, pk, pv, po);

    // Output projection
    dim3 o_grid(DMODEL / 128, NTOK / 128, 1);
    gemm_tf32mma<<<o_grid, 512, GEMM_SMEM_BYTES>>>(
        po, po, po, Wo, Wo, Wo, bo, bo, bo, out, out, out);
}

// round 7
// speedup vs baseline: 3.6041x; 1.2884x over previous
#include <cuda_runtime.h>
#include <cuda_bf16.h>
#include <math.h>
#include <stdint.h>

// Problem constants
#define BATCH   2
#define SEQ     2048
#define DMODEL  1024
#define NHEADS  16
#define HDIM    64
#define NTOK    (BATCH * SEQ)          // 4096

// ---------------------------------------------------------------------------
// Scratch (device globals — no runtime allocation allowed)
// ---------------------------------------------------------------------------
__device__ float g_q[NTOK * DMODEL];
__device__ float g_k[NTOK * DMODEL];
__device__ float g_v[NTOK * DMODEL];
__device__ float g_o[NTOK * DMODEL];

// ---------------------------------------------------------------------------
// Portable (sm_80+) tensor-core helpers: tf32 mma.sync — works on base sm_103
// ---------------------------------------------------------------------------
__device__ __forceinline__ uint32_t tf32_rna(float x) {
    uint32_t r;
    asm("cvt.rna.tf32.f32 %0, %1;" : "=r"(r) : "f"(x));
    return r;
}
__device__ __forceinline__ void split_tf32(float x, uint32_t& hi, uint32_t& lo) {
    hi = tf32_rna(x);
    lo = tf32_rna(x - __uint_as_float(hi));
}

#define MMA_TF32(d, a, b)                                                     \
    asm volatile("mma.sync.aligned.m16n8k8.row.col.f32.tf32.tf32.f32 "        \
        "{%0,%1,%2,%3}, {%4,%5,%6,%7}, {%8,%9}, {%0,%1,%2,%3};"               \
        : "+f"((d)[0]), "+f"((d)[1]), "+f"((d)[2]), "+f"((d)[3])              \
        : "r"((a)[0]), "r"((a)[1]), "r"((a)[2]), "r"((a)[3]),                 \
          "r"((b)[0]), "r"((b)[1]))

// ---------------------------------------------------------------------------
// tf32 GEMM: C[M,N] = rna_tf32(A[M,K]) * rna_tf32(W[N,K])^T + bias[N]
// (unchanged — validated at 104us)
// ---------------------------------------------------------------------------
#define GPITCH 36
#define GTILEF (128 * GPITCH)
#define GEMM_SMEM_BYTES (4 * GTILEF * 4)

__global__ void __launch_bounds__(512) gemm_tf32mma(
    const float* __restrict__ A0, const float* __restrict__ A1, const float* __restrict__ A2,
    const float* __restrict__ W0, const float* __restrict__ W1, const float* __restrict__ W2,
    const float* __restrict__ B0, const float* __restrict__ B1, const float* __restrict__ B2,
    float* __restrict__ C0, float* __restrict__ C1, float* __restrict__ C2)
{
    extern __shared__ __align__(16) float smf[];
    const int tid  = threadIdx.x;
    const int wid  = tid >> 5;
    const int lane = tid & 31;
    const int g    = lane >> 2;
    const int tg   = lane & 3;
    const int wm   = wid >> 2;
    const int wn   = wid & 3;
    const int z    = blockIdx.z;

    const float* A    = (z == 0) ? A0 : ((z == 1) ? A1 : A2);
    const float* W    = (z == 0) ? W0 : ((z == 1) ? W1 : W2);
    const float* bias = (z == 0) ? B0 : ((z == 1) ? B1 : B2);
    float*       C    = (z == 0) ? C0 : ((z == 1) ? C1 : C2);

    const int bm = blockIdx.y * 128;
    const int bn = blockIdx.x * 128;

    const int r0 = tid >> 3;
    const int f4 = tid & 7;

    float acc[2][4][4];
    #pragma unroll
    for (int mt = 0; mt < 2; mt++)
        #pragma unroll
        for (int nt = 0; nt < 4; nt++)
            #pragma unroll
            for (int i = 0; i < 4; i++) acc[mt][nt][i] = 0.f;

    {
        const float* Ag = A + (size_t)bm * DMODEL;
        const float* Wg = W + (size_t)bn * DMODEL;
        float* As = smf;
        float* Bs = smf + GTILEF;
        #pragma unroll
        for (int s = 0; s < 2; s++) {
            const int row = r0 + s * 64;
            float4 a4 = *(const float4*)(Ag + (size_t)row * DMODEL + f4 * 4);
            float4 w4 = *(const float4*)(Wg + (size_t)row * DMODEL + f4 * 4);
            uint32_t* ap = (uint32_t*)(As + row * GPITCH + f4 * 4);
            uint32_t* bp = (uint32_t*)(Bs + row * GPITCH + f4 * 4);
            ap[0] = tf32_rna(a4.x); ap[1] = tf32_rna(a4.y);
            ap[2] = tf32_rna(a4.z); ap[3] = tf32_rna(a4.w);
            bp[0] = tf32_rna(w4.x); bp[1] = tf32_rna(w4.y);
            bp[2] = tf32_rna(w4.z); bp[3] = tf32_rna(w4.w);
        }
    }
    __syncthreads();

    #pragma unroll 1
    for (int c = 0; c < 32; c++) {
        float4 pa[2], pw[2];
        if (c < 31) {
            const float* Ag = A + (size_t)bm * DMODEL + (c + 1) * 32;
            const float* Wg = W + (size_t)bn * DMODEL + (c + 1) * 32;
            #pragma unroll
            for (int s = 0; s < 2; s++) {
                const int row = r0 + s * 64;
                pa[s] = *(const float4*)(Ag + (size_t)row * DMODEL + f4 * 4);
                pw[s] = *(const float4*)(Wg + (size_t)row * DMODEL + f4 * 4);
            }
        }

        const float* As = smf + (c & 1) * (2 * GTILEF);
        const float* Bs = As + GTILEF;
        #pragma unroll
        for (int ks = 0; ks < 4; ks++) {
            const int k0 = ks * 8;
            uint32_t afr[2][4], bfr[4][2];
            #pragma unroll
            for (int mt = 0; mt < 2; mt++) {
                const int r = wm * 32 + mt * 16 + g;
                const uint32_t* Ar = (const uint32_t*)(As + r * GPITCH + k0);
                afr[mt][0] = Ar[tg];
                afr[mt][2] = Ar[tg + 4];
                const uint32_t* Ar8 = (const uint32_t*)(As + (r + 8) * GPITCH + k0);
                afr[mt][1] = Ar8[tg];
                afr[mt][3] = Ar8[tg + 4];
            }
            #pragma unroll
            for (int nt = 0; nt < 4; nt++) {
                const uint32_t* Br =
                    (const uint32_t*)(Bs + (wn * 32 + nt * 8 + g) * GPITCH + k0);
                bfr[nt][0] = Br[tg];
                bfr[nt][1] = Br[tg + 4];
            }
            #pragma unroll
            for (int mt = 0; mt < 2; mt++)
                #pragma unroll
                for (int nt = 0; nt < 4; nt++)
                    MMA_TF32(acc[mt][nt], afr[mt], bfr[nt]);
        }

        if (c < 31) {
            __syncthreads();
            float* Ad = smf + ((c + 1) & 1) * (2 * GTILEF);
            float* Bd = Ad + GTILEF;
            #pragma unroll
            for (int s = 0; s < 2; s++) {
                const int row = r0 + s * 64;
                uint32_t* ap = (uint32_t*)(Ad + row * GPITCH + f4 * 4);
                uint32_t* bp = (uint32_t*)(Bd + row * GPITCH + f4 * 4);
                ap[0] = tf32_rna(pa[s].x); ap[1] = tf32_rna(pa[s].y);
                ap[2] = tf32_rna(pa[s].z); ap[3] = tf32_rna(pa[s].w);
                bp[0] = tf32_rna(pw[s].x); bp[1] = tf32_rna(pw[s].y);
                bp[2] = tf32_rna(pw[s].z); bp[3] = tf32_rna(pw[s].w);
            }
            __syncthreads();
        }
    }

    #pragma unroll
    for (int mt = 0; mt < 2; mt++) {
        const int row = bm + wm * 32 + mt * 16 + g;
        #pragma unroll
        for (int nt = 0; nt < 4; nt++) {
            const int col = bn + wn * 32 + nt * 8 + tg * 2;
            const float2 bv = *(const float2*)(bias + col);
            float2 o0, o1;
            o0.x = acc[mt][nt][0] + bv.x; o0.y = acc[mt][nt][1] + bv.y;
            o1.x = acc[mt][nt][2] + bv.x; o1.y = acc[mt][nt][3] + bv.y;
            *(float2*)(C + (size_t)row * DMODEL + col) = o0;
            *(float2*)(C + (size_t)(row + 8) * DMODEL + col) = o1;
        }
    }
}

// ---------------------------------------------------------------------------
// RoPE: one warp per (b, t, h). (unchanged — validated)
// ---------------------------------------------------------------------------
__global__ __launch_bounds__(256) void rope_kernel(float* __restrict__ q,
                                                   float* __restrict__ k)
{
    const int gtid = blockIdx.x * blockDim.x + threadIdx.x;
    const int warp = gtid >> 5;
    const int lane = gtid & 31;
    const int h = warp % NHEADS;
    const int t = (warp / NHEADS) % SEQ;
    const int b = warp / (NHEADS * SEQ);

    const float inv_freq = powf(10000.0f, -(float)(2 * lane) / (float)HDIM);
    const float ang = (float)t * inv_freq;
    const float s = sinf(ang);
    const float c = cosf(ang);

    const size_t base = ((size_t)(b * SEQ + t)) * DMODEL + h * HDIM;

    float q1 = q[base + lane], q2 = q[base + lane + 32];
    q[base + lane]      = q1 * c - q2 * s;
    q[base + lane + 32] = q2 * c + q1 * s;

    float k1 = k[base + lane], k2 = k[base + lane + 32];
    k[base + lane]      = k1 * c - k2 * s;
    k[base + lane + 32] = k2 * c + k1 * s;
}

// ---------------------------------------------------------------------------
// Tensor-core flash attention, round 6: hi/lo splits hoisted to tile load
// (SMEM k_hi/k_lo/v_hi/v_lo), Q kept fp32 in regs and split per-ks.
// __launch_bounds__(256, 2) -> <=128 regs -> 2 CTAs/SM, 16 warps.
// ---------------------------------------------------------------------------
#define AP 68
// k_hi, k_lo, v_hi, v_lo: 64*AP each; p_s: 128*AP
#define ATTN_SMEM_BYTES ((4 * 64 * AP + 128 * AP) * 4)   // 104448

__global__ void __launch_bounds__(256, 2) attn_tc(
    const float* __restrict__ Q, const float* __restrict__ K,
    const float* __restrict__ V, float* __restrict__ O)
{
    extern __shared__ __align__(16) float sm[];
    float* k_hi = sm;                    // [64][AP]  k[key][d] hi
    float* k_lo = sm + 64 * AP;          // [64][AP]  k[key][d] lo
    float* v_hi = sm + 128 * AP;         // [64][AP]  v[d][key] hi (transposed)
    float* v_lo = sm + 192 * AP;         // [64][AP]  v[d][key] lo
    float* p_s  = sm + 256 * AP;         // [128][AP] p[qrow][key]

    const int tid  = threadIdx.x;
    const int w    = tid >> 5;
    const int lane = tid & 31;
    const int g    = lane >> 2;      // 0..7
    const int tg   = lane & 3;       // 0..3
    const int b    = blockIdx.z;
    const int h    = blockIdx.y;
    const int q0   = blockIdx.x * 128;

    // ---- Q fragments, fp32, register-resident (split on the fly per ks)
    float qf[8][4];
    {
        const float* Qb = Q + ((size_t)(b * SEQ + q0 + w * 16)) * DMODEL + h * HDIM;
        #pragma unroll
        for (int ks = 0; ks < 8; ks++) {
            const int c0 = ks * 8 + tg;
            qf[ks][0] = Qb[(size_t)g * DMODEL + c0];
            qf[ks][1] = Qb[(size_t)(g + 8) * DMODEL + c0];
            qf[ks][2] = Qb[(size_t)g * DMODEL + c0 + 4];
            qf[ks][3] = Qb[(size_t)(g + 8) * DMODEL + c0 + 4];
        }
    }

    float out[8][4];
    #pragma unroll
    for (int nt = 0; nt < 8; nt++)
        #pragma unroll
        for (int i = 0; i < 4; i++) out[nt][i] = 0.f;
    float m0 = -INFINITY, m1 = -INFINITY, l0 = 0.f, l1 = 0.f;

    // V loader mapping: thread -> (key, dgroup)
    const int vkey = tid & 63;
    const int vdg  = tid >> 6;       // 0..3, 16 dims each

    #pragma unroll 1
    for (int j0 = 0; j0 < SEQ; j0 += 64) {
        __syncthreads();
        // ---- load K tile, split hi/lo at load time
        #pragma unroll
        for (int it = 0; it < 4; it++) {
            const int i   = it * 256 + tid;
            const int key = i >> 4;
            const int c4  = (i & 15) * 4;
            const float4 kk = *(const float4*)(
                K + ((size_t)(b * SEQ + j0 + key)) * DMODEL + h * HDIM + c4);
            uint32_t h4[4], l4[4];
            split_tf32(kk.x, h4[0], l4[0]);
            split_tf32(kk.y, h4[1], l4[1]);
            split_tf32(kk.z, h4[2], l4[2]);
            split_tf32(kk.w, h4[3], l4[3]);
            *(uint4*)(k_hi + key * AP + c4) = make_uint4(h4[0], h4[1], h4[2], h4[3]);
            *(uint4*)(k_lo + key * AP + c4) = make_uint4(l4[0], l4[1], l4[2], l4[3]);
        }
        // ---- load V tile transposed, split hi/lo
        {
            const float* Vg = V + ((size_t)(b * SEQ + j0 + vkey)) * DMODEL + h * HDIM + vdg * 16;
            #pragma unroll
            for (int e = 0; e < 4; e++) {
                const float4 vv = *(const float4*)(Vg + e * 4);
                const int d0 = vdg * 16 + e * 4;
                uint32_t hh, ll;
                split_tf32(vv.x, hh, ll);
                v_hi[(d0 + 0) * AP + vkey] = __uint_as_float(hh);
                v_lo[(d0 + 0) * AP + vkey] = __uint_as_float(ll);
                split_tf32(vv.y, hh, ll);
                v_hi[(d0 + 1) * AP + vkey] = __uint_as_float(hh);
                v_lo[(d0 + 1) * AP + vkey] = __uint_as_float(ll);
                split_tf32(vv.z, hh, ll);
                v_hi[(d0 + 2) * AP + vkey] = __uint_as_float(hh);
                v_lo[(d0 + 2) * AP + vkey] = __uint_as_float(ll);
                split_tf32(vv.w, hh, ll);
                v_hi[(d0 + 3) * AP + vkey] = __uint_as_float(hh);
                v_lo[(d0 + 3) * AP + vkey] = __uint_as_float(ll);
            }
        }
        __syncthreads();

        // ---- S = Q K^T (3xtf32, splits from SMEM)
        float s[8][4];
        #pragma unroll
        for (int nt = 0; nt < 8; nt++)
            #pragma unroll
            for (int i = 0; i < 4; i++) s[nt][i] = 0.f;

        #pragma unroll
        for (int ks = 0; ks < 8; ks++) {
            uint32_t ah[4], al[4];
            split_tf32(qf[ks][0], ah[0], al[0]);
            split_tf32(qf[ks][1], ah[1], al[1]);
            split_tf32(qf[ks][2], ah[2], al[2]);
            split_tf32(qf[ks][3], ah[3], al[3]);
            #pragma unroll
            for (int nt = 0; nt < 8; nt++) {
                const int off = (nt * 8 + g) * AP + ks * 8 + tg;
                uint32_t bh[2], bl[2];
                bh[0] = ((const uint32_t*)k_hi)[off];
                bh[1] = ((const uint32_t*)k_hi)[off + 4];
                bl[0] = ((const uint32_t*)k_lo)[off];
                bl[1] = ((const uint32_t*)k_lo)[off + 4];
                MMA_TF32(s[nt], ah, bh);
                MMA_TF32(s[nt], al, bh);
                MMA_TF32(s[nt], ah, bl);
            }
        }

        // ---- online softmax (rows g and g+8)
        const float scale = 0.125f;
        float mt0 = -INFINITY, mt1 = -INFINITY;
        #pragma unroll
        for (int nt = 0; nt < 8; nt++) {
            s[nt][0] *= scale; s[nt][1] *= scale;
            s[nt][2] *= scale; s[nt][3] *= scale;
            mt0 = fmaxf(mt0, fmaxf(s[nt][0], s[nt][1]));
            mt1 = fmaxf(mt1, fmaxf(s[nt][2], s[nt][3]));
        }
        mt0 = fmaxf(mt0, __shfl_xor_sync(0xffffffffu, mt0, 1));
        mt0 = fmaxf(mt0, __shfl_xor_sync(0xffffffffu, mt0, 2));
        mt1 = fmaxf(mt1, __shfl_xor_sync(0xffffffffu, mt1, 1));
        mt1 = fmaxf(mt1, __shfl_xor_sync(0xffffffffu, mt1, 2));

        const float mn0 = fmaxf(m0, mt0);
        const float mn1 = fmaxf(m1, mt1);
        const float a0 = __expf(m0 - mn0);
        const float a1 = __expf(m1 - mn1);

        float rs0 = 0.f, rs1 = 0.f;
        float* pr0 = p_s + (w * 16 + g) * AP;
        float* pr1 = p_s + (w * 16 + g + 8) * AP;
        #pragma unroll
        for (int nt = 0; nt < 8; nt++) {
            const float p0 = __expf(s[nt][0] - mn0);
            const float p1 = __expf(s[nt][1] - mn0);
            const float p2 = __expf(s[nt][2] - mn1);
            const float p3 = __expf(s[nt][3] - mn1);
            rs0 += p0 + p1;
            rs1 += p2 + p3;
            *(float2*)(pr0 + nt * 8 + 2 * tg) = make_float2(p0, p1);
            *(float2*)(pr1 + nt * 8 + 2 * tg) = make_float2(p2, p3);
        }
        rs0 += __shfl_xor_sync(0xffffffffu, rs0, 1);
        rs0 += __shfl_xor_sync(0xffffffffu, rs0, 2);
        rs1 += __shfl_xor_sync(0xffffffffu, rs1, 1);
        rs1 += __shfl_xor_sync(0xffffffffu, rs1, 2);

        l0 = l0 * a0 + rs0;
        l1 = l1 * a1 + rs1;
        m0 = mn0;
        m1 = mn1;

        #pragma unroll
        for (int nt = 0; nt < 8; nt++) {
            out[nt][0] *= a0; out[nt][1] *= a0;
            out[nt][2] *= a1; out[nt][3] *= a1;
        }
        __syncwarp();

        // ---- out += P V (3xtf32); A-frag split per ks, B-frags from SMEM hi/lo
        #pragma unroll
        for (int ks = 0; ks < 8; ks++) {
            const float af0 = p_s[(w * 16 + g) * AP + ks * 8 + tg];
            const float af1 = p_s[(w * 16 + g + 8) * AP + ks * 8 + tg];
            const float af2 = p_s[(w * 16 + g) * AP + ks * 8 + tg + 4];
            const float af3 = p_s[(w * 16 + g + 8) * AP + ks * 8 + tg + 4];
            uint32_t ah[4], al[4];
            split_tf32(af0, ah[0], al[0]);
            split_tf32(af1, ah[1], al[1]);
            split_tf32(af2, ah[2], al[2]);
            split_tf32(af3, ah[3], al[3]);
            #pragma unroll
            for (int nt = 0; nt < 8; nt++) {
                const int off = (nt * 8 + g) * AP + ks * 8 + tg;
                uint32_t bh[2], bl[2];
                bh[0] = ((const uint32_t*)v_hi)[off];
                bh[1] = ((const uint32_t*)v_hi)[off + 4];
                bl[0] = ((const uint32_t*)v_lo)[off];
                bl[1] = ((const uint32_t*)v_lo)[off + 4];
                MMA_TF32(out[nt], ah, bh);
                MMA_TF32(out[nt], al, bh);
                MMA_TF32(out[nt], ah, bl);
            }
        }
    }

    // ---- epilogue: normalize and store
    const float inv0 = 1.f / l0;
    const float inv1 = 1.f / l1;
    const size_t tok0 = (size_t)(b * SEQ + q0 + w * 16 + g);
    #pragma unroll
    for (int nt = 0; nt < 8; nt++) {
        const int col = h * HDIM + nt * 8 + 2 * tg;
        *(float2*)(O + tok0 * DMODEL + col) =
            make_float2(out[nt][0] * inv0, out[nt][1] * inv0);
        *(float2*)(O + (tok0 + 8) * DMODEL + col) =
            make_float2(out[nt][2] * inv1, out[nt][3] * inv1);
    }
}

// ---------------------------------------------------------------------------
// Launch
// Inputs (metadata order): q_in, k_in, v_in, Wq, bq, Wk, bk, Wv, bv, Wo, bo
// ---------------------------------------------------------------------------
extern "C" void kernel_launch(void* const* d_in, const int* in_sizes, int n_in,
                              void* d_out, int out_size)
{
    const float* q_in = (const float*)d_in[0];
    const float* k_in = (const float*)d_in[1];
    const float* v_in = (const float*)d_in[2];
    const float* Wq = (const float*)d_in[3];
    const float* bq = (const float*)d_in[4];
    const float* Wk = (const float*)d_in[5];
    const float* bk = (const float*)d_in[6];
    const float* Wv = (const float*)d_in[7];
    const float* bv = (const float*)d_in[8];
    const float* Wo = (const float*)d_in[9];
    const float* bo = (const float*)d_in[10];
    float* out = (float*)d_out;

    float *pq, *pk, *pv, *po;
    cudaGetSymbolAddress((void**)&pq, g_q);
    cudaGetSymbolAddress((void**)&pk, g_k);
    cudaGetSymbolAddress((void**)&pv, g_v);
    cudaGetSymbolAddress((void**)&po, g_o);

    cudaFuncSetAttribute(gemm_tf32mma,
                         cudaFuncAttributeMaxDynamicSharedMemorySize, GEMM_SMEM_BYTES);
    cudaFuncSetAttribute(attn_tc,
                         cudaFuncAttributeMaxDynamicSharedMemorySize, ATTN_SMEM_BYTES);

    // Fused Q/K/V projections
    dim3 qkv_grid(DMODEL / 128, NTOK / 128, 3);
    gemm_tf32mma<<<qkv_grid, 512, GEMM_SMEM_BYTES>>>(
        q_in, k_in, v_in, Wq, Wk, Wv, bq, bk, bv, pq, pk, pv);

    rope_kernel<<<(BATCH * SEQ * NHEADS) / 8, 256>>>(pq, pk);

    // Tensor-core flash attention
    dim3 attn_grid(SEQ / 128, NHEADS, BATCH);     // (16, 16, 2)
    attn_tc<<<attn_grid, 256, ATTN_SMEM_BYTES>>>(pq, pk, pv, po);

    // Output projection
    dim3 o_grid(DMODEL / 128, NTOK / 128, 1);
    gemm_tf32mma<<<o_grid, 512, GEMM_SMEM_BYTES>>>(
        po, po, po, Wo, Wo, Wo, bo, bo, bo, out, out, out);
}